// round 15
// baseline (speedup 1.0000x reference)
#include <cuda_runtime.h>
#include <math.h>
#include <stdint.h>

// ---------------- problem constants ----------------
#define T_LEN   1024
#define BATCH   8
#define TBROWS  8192          // T*B
#define DMODEL  256
#define NHEAD   16
#define HDIM    16
#define DFFN    2048
#define NNODES  81
#define INDIM   162
#define KPAD_FC 192           // 162 padded to multiple of 32

// ---------------- scratch (static device memory; allocation-free) ----------
__device__ float g_Ahat [NNODES * NNODES];
__device__ float g_srcp [TBROWS * KPAD_FC];         // padded+rounded src; pad stays 0
__device__ float g_pe   [T_LEN * DMODEL];           // positional encoding table
__device__ float g_x    [TBROWS * DMODEL];          // fc + PE (residual + qkv input)
__device__ float g_qkv  [TBROWS * 3 * DMODEL];      // fused q|k|v, stride 768
__device__ float g_ctx  [TBROWS * DMODEL];          // attention out
__device__ float g_x1   [TBROWS * DMODEL];          // post-LN1 (ffn1 input + ffn2 residual)
__device__ float g_h    [TBROWS * DFFN];            // ffn hidden
__device__ float g_x2   [TBROWS * DMODEL];          // pre-LN2 -> post-LN2 in place

// prepped weights (K-major [N,K], tf32-rounded)
__device__ float g_weffT[DMODEL * KPAD_FC];         // fused GCN+fc weight; k>=162 stays 0
__device__ float g_beff [DMODEL];
__device__ float g_qkvT [3 * DMODEL * DMODEL];      // [768,256]
__device__ float g_bqkv [3 * DMODEL];
__device__ float g_woT  [DMODEL * DMODEL];          // [256,256]
__device__ float g_fw1T [DFFN * DMODEL];            // [2048,256]
__device__ float g_fw2T [DMODEL * DFFN];            // [256,2048]
__device__ float g_decT [256 * DMODEL];             // rows>=162 stay 0

// ---------------- helpers ----------------
__device__ __forceinline__ uint32_t smem_u32(const void* p) {
    return (uint32_t)__cvta_generic_to_shared(p);
}
__device__ __forceinline__ void cp16(uint32_t s, const void* g) {
    asm volatile("cp.async.cg.shared.global [%0], [%1], 16;\n" :: "r"(s), "l"(g));
}
__device__ __forceinline__ void cp_commit() {
    asm volatile("cp.async.commit_group;\n" ::: "memory");
}
template <int N>
__device__ __forceinline__ void cp_wait() {
    asm volatile("cp.async.wait_group %0;\n" :: "n"(N) : "memory");
}
__device__ __forceinline__ uint32_t f2tf32(float f) {
    uint32_t u;
    asm("cvt.rna.tf32.f32 %0, %1;" : "=r"(u) : "f"(f));
    return u;
}
__device__ __forceinline__ float tf32r(float f) { return __uint_as_float(f2tf32(f)); }

__device__ __forceinline__ void ldsm4(uint32_t& r0, uint32_t& r1, uint32_t& r2,
                                      uint32_t& r3, uint32_t addr) {
    asm volatile("ldmatrix.sync.aligned.m8n8.x4.shared.b16 {%0,%1,%2,%3}, [%4];"
                 : "=r"(r0), "=r"(r1), "=r"(r2), "=r"(r3) : "r"(addr));
}

#define MMA_TF32(accv, a0, a1, a2, a3, b0, b1) \
    asm volatile( \
        "mma.sync.aligned.m16n8k8.row.col.f32.tf32.tf32.f32 " \
        "{%0,%1,%2,%3}, {%4,%5,%6,%7}, {%8,%9}, {%0,%1,%2,%3};" \
        : "+f"((accv)[0]), "+f"((accv)[1]), "+f"((accv)[2]), "+f"((accv)[3]) \
        : "r"(a0), "r"(a1), "r"(a2), "r"(a3), "r"(b0), "r"(b1))

// ---------------- A_hat = D^-1/2 (A + I) D^-1/2 ----------------
__global__ void build_ahat_kernel(const int* __restrict__ ei, int E,
                                  float* __restrict__ Ahat) {
    __shared__ float A[NNODES * NNODES];
    __shared__ float dinv[NNODES];
    int tid = threadIdx.x, nt = blockDim.x;
    for (int i = tid; i < NNODES * NNODES; i += nt) A[i] = 0.f;
    __syncthreads();
    for (int e = tid; e < E; e += nt) {
        int r = ei[e];
        int c = ei[E + e];
        atomicAdd(&A[c * NNODES + r], 1.0f);
    }
    __syncthreads();
    for (int i = tid; i < NNODES; i += nt) A[i * NNODES + i] += 1.0f;
    __syncthreads();
    for (int i = tid; i < NNODES; i += nt) {
        float s = 0.f;
        for (int j = 0; j < NNODES; j++) s += A[i * NNODES + j];
        dinv[i] = (s > 0.f) ? rsqrtf(s) : 0.f;
    }
    __syncthreads();
    for (int idx = tid; idx < NNODES * NNODES; idx += nt) {
        int i = idx / NNODES, j = idx % NNODES;
        Ahat[idx] = dinv[i] * A[idx] * dinv[j];
    }
}

// ---------------- fold GCN into fc ----------------
__global__ void weff_kernel(const float* __restrict__ Ahat,
                            const float* __restrict__ gw,
                            const float* __restrict__ gb,
                            const float* __restrict__ fc_w,
                            const float* __restrict__ fc_b,
                            float* __restrict__ weffT, float* __restrict__ beff) {
    int k = blockIdx.x;              // 0..161
    int col = threadIdx.x;           // 0..255
    int ck = k / NNODES, jk = k % NNODES;
    float s0 = 0.f, s1 = 0.f;
    #pragma unroll 3
    for (int i = 0; i < NNODES; i++) {
        float a = Ahat[i * NNODES + jk];
        s0 += a * fc_w[i * DMODEL + col];
        s1 += a * fc_w[(NNODES + i) * DMODEL + col];
    }
    float w0 = gw[ck * 2 + 0], w1 = gw[ck * 2 + 1];
    weffT[col * KPAD_FC + k] = tf32r(w0 * s0 + w1 * s1);
    if (k == 0) {
        float bsum = fc_b[col];
        for (int n = 0; n < INDIM; n++)
            bsum += gb[n / NNODES] * fc_w[n * DMODEL + col];
        beff[col] = bsum;
    }
}

// ---------------- fused weight prep + src repack + PE table ----------------
#define R_W    65536                     // 256*256
#define R_FFN  524288                    // 256*2048
#define R_DEC  41472                     // 256*162
#define R_SRC  (TBROWS * KPAD_FC)        // 1572864
#define R_PE   (T_LEN * DMODEL)          // 262144
#define PREP_TOTAL (4*R_W + 2*R_FFN + R_DEC + 768 + R_SRC + R_PE)

__global__ void prep_kernel(const float* __restrict__ wq, const float* __restrict__ wk,
                            const float* __restrict__ wv, const float* __restrict__ wo,
                            const float* __restrict__ fw1, const float* __restrict__ fw2,
                            const float* __restrict__ dw,
                            const float* __restrict__ bq, const float* __restrict__ bk,
                            const float* __restrict__ bv,
                            const float* __restrict__ src,
                            float* __restrict__ qkvT, float* __restrict__ woT,
                            float* __restrict__ fw1T, float* __restrict__ fw2T,
                            float* __restrict__ decT, float* __restrict__ bqkv,
                            float* __restrict__ srcp, float* __restrict__ pe) {
    const float NEG = -0.03597789206f;                     // -ln(10000)/256
    int idx = blockIdx.x * 256 + threadIdx.x;
    if (idx < R_SRC) {                                     // src repack+round
        int tb = idx / KPAD_FC, c = idx - tb * KPAD_FC;
        srcp[idx] = (c < INDIM) ? tf32r(src[tb * INDIM + c]) : 0.f;
        return;
    }
    idx -= R_SRC;
    if (idx < R_PE) {                                      // PE table (exact math)
        int t = idx >> 8, c = idx & 255;
        float dv = expf(NEG * (float)(c & ~1));
        float ang = (float)t * dv;
        pe[idx] = (c & 1) ? cosf(ang) : sinf(ang);
        return;
    }
    idx -= R_PE;
    if (idx < 3 * R_W) {
        int which = idx / R_W, r = idx % R_W;
        int k = r >> 8, n = r & 255;
        const float* w = (which == 0) ? wq : (which == 1) ? wk : wv;
        qkvT[which * R_W + n * 256 + k] = tf32r(w[r]);
        return;
    }
    idx -= 3 * R_W;
    if (idx < R_W) {
        int k = idx >> 8, n = idx & 255;
        woT[n * 256 + k] = tf32r(wo[idx]);
        return;
    }
    idx -= R_W;
    if (idx < R_FFN) {
        int k = idx >> 11, n = idx & 2047;
        fw1T[(size_t)n * 256 + k] = tf32r(fw1[idx]);
        return;
    }
    idx -= R_FFN;
    if (idx < R_FFN) {
        int k = idx >> 8, n = idx & 255;
        fw2T[(size_t)n * 2048 + k] = tf32r(fw2[idx]);
        return;
    }
    idx -= R_FFN;
    if (idx < R_DEC) {
        int k = idx / 162, n = idx % 162;
        decT[n * 256 + k] = tf32r(dw[idx]);
        return;
    }
    idx -= R_DEC;
    if (idx < 768) {
        bqkv[idx] = (idx < 256) ? bq[idx] : (idx < 512) ? bk[idx - 256] : bv[idx - 512];
    }
}

// ------- unified big-tile GEMM: 128x128, 3-stage ring, 512 threads ---------
// 16 warps in 4x4 grid; warp = 32 rows x 32 cols (same 2.67 MMA:LDSM ratio,
// double the warps/SM for latency hiding).
// A consumed as raw fp32 bits (hardware tf32 truncation).
// EPI: 0 bias, 1 bias+PE-table via res, 2 bias+relu, 3 bias+res,
//      4 bias+masked (n<Nvalid).
#define SROW 36
#define BMB 128
#define BNB 128
#define STAGEB ((BMB + BNB) * SROW)      // 9216 floats
#define GEMMB_SMEM (3 * STAGEB * 4)      // 110592 bytes -> 1 block/SM

template <int EPI>
__global__ void __launch_bounds__(512, 1)
mma_gemm_big(const float* __restrict__ A, const float* __restrict__ Bt,
             const float* __restrict__ bias, const float* __restrict__ res,
             float* __restrict__ C, int K, int Cstride, int Nvalid) {
    extern __shared__ float sm[];
    int tid = threadIdx.x;
    int m0 = blockIdx.y * BMB;
    int n0 = blockIdx.x * BNB;
    int warp = tid >> 5, lane = tid & 31;
    int wm = warp & 3, wn = warp >> 2;          // 4x4: warp = 32 rows x 32 cols
    int g = lane >> 2, tg = lane & 3;

    uint32_t a_off = (uint32_t)((lane & 15) * 144 + (lane >> 4) * 16);
    uint32_t b_off = (uint32_t)((((lane >> 4) << 3) + (lane & 7)) * 144
                                + ((lane >> 3) & 1) * 16);

    const float* A0 = A + (size_t)m0 * K;
    const float* B0 = Bt + (size_t)n0 * K;

    float acc[2][4][4];
    #pragma unroll
    for (int i = 0; i < 2; i++)
        #pragma unroll
        for (int j = 0; j < 4; j++)
            #pragma unroll
            for (int q = 0; q < 4; q++) acc[i][j][q] = 0.f;

    auto load = [&](int c) {
        uint32_t sa = smem_u32(sm) + (uint32_t)((c % 3) * STAGEB * 4);
        uint32_t sb = sa + BMB * SROW * 4;
        const float* Ab = A0 + c * 32;
        const float* Bb = B0 + c * 32;
        #pragma unroll
        for (int i = 0; i < 2; i++) {            // A: 128 rows x 8 slots = 1024
            int id = tid + i * 512;
            int r = id >> 3, sl = id & 7;
            cp16(sa + r * 144 + sl * 16, Ab + (size_t)r * K + sl * 4);
        }
        #pragma unroll
        for (int i = 0; i < 2; i++) {            // B: 128 rows x 8 slots = 1024
            int id = tid + i * 512;
            int r = id >> 3, sl = id & 7;
            cp16(sb + r * 144 + sl * 16, Bb + (size_t)r * K + sl * 4);
        }
    };

    int NC = K >> 5;
    load(0); cp_commit();
    load(1); cp_commit();

    for (int c = 0; c < NC; c++) {
        cp_wait<1>();                 // group c complete (<=1 newer pending)
        __syncthreads();              // all warps done with stage (c-1)%3
        if (c + 2 < NC) load(c + 2);  // prefetch into stage (c+2)%3 == (c-1)%3
        cp_commit();
        uint32_t sA = smem_u32(sm) + (uint32_t)((c % 3) * STAGEB * 4);
        uint32_t sB = sA + BMB * SROW * 4;
        #pragma unroll
        for (int ks = 0; ks < 4; ks++) {
            uint32_t k0b = ks * 32;
            uint32_t af[2][4], bf[4][2];
            #pragma unroll
            for (int mf = 0; mf < 2; mf++) {
                uint32_t rm = wm * 32 + mf * 16;
                ldsm4(af[mf][0], af[mf][1], af[mf][2], af[mf][3],
                      sA + rm * 144 + k0b + a_off);
            }
            #pragma unroll
            for (int nfp = 0; nfp < 2; nfp++) {
                uint32_t cn = wn * 32 + nfp * 16;
                ldsm4(bf[2 * nfp][0], bf[2 * nfp][1],
                      bf[2 * nfp + 1][0], bf[2 * nfp + 1][1],
                      sB + cn * 144 + k0b + b_off);
            }
            #pragma unroll
            for (int mf = 0; mf < 2; mf++)
                #pragma unroll
                for (int nf = 0; nf < 4; nf++)
                    MMA_TF32(acc[mf][nf], af[mf][0], af[mf][1], af[mf][2], af[mf][3],
                             bf[nf][0], bf[nf][1]);
        }
    }

    #pragma unroll
    for (int mf = 0; mf < 2; mf++) {
        #pragma unroll
        for (int half = 0; half < 2; half++) {
            int gr = m0 + wm * 32 + mf * 16 + g + half * 8;
            #pragma unroll
            for (int nf = 0; nf < 4; nf++) {
                int cb = n0 + wn * 32 + nf * 8 + 2 * tg;
                if (EPI == 4) {
                    float v0 = acc[mf][nf][half * 2 + 0];
                    float v1 = acc[mf][nf][half * 2 + 1];
                    if (cb < Nvalid)
                        C[(size_t)gr * Cstride + cb]     = v0 + bias[cb];
                    if (cb + 1 < Nvalid)
                        C[(size_t)gr * Cstride + cb + 1] = v1 + bias[cb + 1];
                } else {
                    float v0 = acc[mf][nf][half * 2 + 0] + bias[cb];
                    float v1 = acc[mf][nf][half * 2 + 1] + bias[cb + 1];
                    if (EPI == 3) {
                        v0 += res[(size_t)gr * Cstride + cb];
                        v1 += res[(size_t)gr * Cstride + cb + 1];
                    }
                    if (EPI == 2) { v0 = fmaxf(v0, 0.f); v1 = fmaxf(v1, 0.f); }
                    if (EPI == 1) {
                        int t = gr >> 3;
                        float2 p = *(const float2*)&res[(size_t)t * DMODEL + cb];
                        v0 += p.x;
                        v1 += p.y;
                    }
                    *(float2*)&C[(size_t)gr * Cstride + cb] = make_float2(v0, v1);
                }
            }
        }
    }
}

// ---------------- tensor-core causal flash attention ----------------
#define QKV_STRIDE (3 * DMODEL)
#define QK_ST 20
#define PS_ST 68

__global__ void __launch_bounds__(128)
attn_mma_kernel(const float* __restrict__ qkv, float* __restrict__ ctx) {
    __shared__ float Qs[64 * QK_ST];
    __shared__ float Ks[64 * QK_ST];
    __shared__ float Vt[16 * PS_ST];
    __shared__ float Ps[64 * PS_ST];
    int bh = blockIdx.x;
    int b = bh >> 4, h = bh & 15;
    int qt = blockIdx.y;
    int tid = threadIdx.x;
    int w = tid >> 5, lane = tid & 31;
    int g = lane >> 2, tg = lane & 3;
    int co = h * HDIM;

    for (int idx = tid; idx < 256; idx += 128) {
        int r = idx >> 2, qd = idx & 3;
        int t = qt * 64 + r;
        float4 q = *((const float4*)(qkv + ((size_t)(t * BATCH + b)) * QKV_STRIDE + co) + qd);
        *(float4*)&Qs[r * QK_ST + qd * 4] = q;
    }
    __syncthreads();

    uint32_t qa[2][4];
    {
        int r = w * 16 + g;
        #pragma unroll
        for (int ks = 0; ks < 2; ks++) {
            qa[ks][0] = __float_as_uint(Qs[r       * QK_ST + ks * 8 + tg]);
            qa[ks][1] = __float_as_uint(Qs[(r + 8) * QK_ST + ks * 8 + tg]);
            qa[ks][2] = __float_as_uint(Qs[r       * QK_ST + ks * 8 + tg + 4]);
            qa[ks][3] = __float_as_uint(Qs[(r + 8) * QK_ST + ks * 8 + tg + 4]);
        }
    }

    float m0 = -1e30f, m1 = -1e30f, l0 = 0.f, l1 = 0.f;
    float o[2][4] = {};
    int row0 = qt * 64 + w * 16 + g;
    int row1 = row0 + 8;

    for (int kt = 0; kt <= qt; kt++) {
        for (int idx = tid; idx < 256; idx += 128) {
            int r = idx >> 2, qd = idx & 3;
            int t = kt * 64 + r;
            const float* base = qkv + ((size_t)(t * BATCH + b)) * QKV_STRIDE + co;
            float4 kq = *((const float4*)(base + DMODEL) + qd);
            float4 vq = *((const float4*)(base + 2 * DMODEL) + qd);
            *(float4*)&Ks[r * QK_ST + qd * 4] = kq;
            Vt[(qd * 4 + 0) * PS_ST + r] = vq.x;
            Vt[(qd * 4 + 1) * PS_ST + r] = vq.y;
            Vt[(qd * 4 + 2) * PS_ST + r] = vq.z;
            Vt[(qd * 4 + 3) * PS_ST + r] = vq.w;
        }
        __syncthreads();

        float s[8][4] = {};
        #pragma unroll
        for (int ks = 0; ks < 2; ks++) {
            #pragma unroll
            for (int nf = 0; nf < 8; nf++) {
                uint32_t b0 = __float_as_uint(Ks[(nf * 8 + g) * QK_ST + ks * 8 + tg]);
                uint32_t b1 = __float_as_uint(Ks[(nf * 8 + g) * QK_ST + ks * 8 + tg + 4]);
                MMA_TF32(s[nf], qa[ks][0], qa[ks][1], qa[ks][2], qa[ks][3], b0, b1);
            }
        }

        if (kt == qt) {
            #pragma unroll
            for (int nf = 0; nf < 8; nf++) {
                int c = kt * 64 + nf * 8 + 2 * tg;
                s[nf][0] = (c     <= row0) ? s[nf][0] * 0.25f : -1e30f;
                s[nf][1] = (c + 1 <= row0) ? s[nf][1] * 0.25f : -1e30f;
                s[nf][2] = (c     <= row1) ? s[nf][2] * 0.25f : -1e30f;
                s[nf][3] = (c + 1 <= row1) ? s[nf][3] * 0.25f : -1e30f;
            }
        } else {
            #pragma unroll
            for (int nf = 0; nf < 8; nf++) {
                s[nf][0] *= 0.25f; s[nf][1] *= 0.25f;
                s[nf][2] *= 0.25f; s[nf][3] *= 0.25f;
            }
        }

        float mx0 = -1e30f, mx1 = -1e30f;
        #pragma unroll
        for (int nf = 0; nf < 8; nf++) {
            mx0 = fmaxf(mx0, fmaxf(s[nf][0], s[nf][1]));
            mx1 = fmaxf(mx1, fmaxf(s[nf][2], s[nf][3]));
        }
        mx0 = fmaxf(mx0, __shfl_xor_sync(0xffffffffu, mx0, 1));
        mx0 = fmaxf(mx0, __shfl_xor_sync(0xffffffffu, mx0, 2));
        mx1 = fmaxf(mx1, __shfl_xor_sync(0xffffffffu, mx1, 1));
        mx1 = fmaxf(mx1, __shfl_xor_sync(0xffffffffu, mx1, 2));

        float mn0 = fmaxf(m0, mx0), mn1 = fmaxf(m1, mx1);
        float al0 = __expf(m0 - mn0), al1 = __expf(m1 - mn1);
        m0 = mn0; m1 = mn1;

        float sum0 = 0.f, sum1 = 0.f;
        int pr0 = w * 16 + g, pr1 = pr0 + 8;
        #pragma unroll
        for (int nf = 0; nf < 8; nf++) {
            float p0 = __expf(s[nf][0] - mn0);
            float p1 = __expf(s[nf][1] - mn0);
            float p2 = __expf(s[nf][2] - mn1);
            float p3 = __expf(s[nf][3] - mn1);
            sum0 += p0 + p1;
            sum1 += p2 + p3;
            *(float2*)&Ps[pr0 * PS_ST + nf * 8 + 2 * tg] = make_float2(p0, p1);
            *(float2*)&Ps[pr1 * PS_ST + nf * 8 + 2 * tg] = make_float2(p2, p3);
        }
        sum0 += __shfl_xor_sync(0xffffffffu, sum0, 1);
        sum0 += __shfl_xor_sync(0xffffffffu, sum0, 2);
        sum1 += __shfl_xor_sync(0xffffffffu, sum1, 1);
        sum1 += __shfl_xor_sync(0xffffffffu, sum1, 2);
        l0 = l0 * al0 + sum0;
        l1 = l1 * al1 + sum1;

        #pragma unroll
        for (int nf = 0; nf < 2; nf++) {
            o[nf][0] *= al0; o[nf][1] *= al0;
            o[nf][2] *= al1; o[nf][3] *= al1;
        }
        __syncwarp();

        #pragma unroll
        for (int ks = 0; ks < 8; ks++) {
            uint32_t pa0 = __float_as_uint(Ps[pr0 * PS_ST + ks * 8 + tg]);
            uint32_t pa1 = __float_as_uint(Ps[pr1 * PS_ST + ks * 8 + tg]);
            uint32_t pa2 = __float_as_uint(Ps[pr0 * PS_ST + ks * 8 + tg + 4]);
            uint32_t pa3 = __float_as_uint(Ps[pr1 * PS_ST + ks * 8 + tg + 4]);
            #pragma unroll
            for (int nf = 0; nf < 2; nf++) {
                uint32_t b0 = __float_as_uint(Vt[(nf * 8 + g) * PS_ST + ks * 8 + tg]);
                uint32_t b1 = __float_as_uint(Vt[(nf * 8 + g) * PS_ST + ks * 8 + tg + 4]);
                MMA_TF32(o[nf], pa0, pa1, pa2, pa3, b0, b1);
            }
        }
        __syncthreads();
    }

    float inv0 = 1.f / l0, inv1 = 1.f / l1;
    float* out0 = ctx + ((size_t)(row0 * BATCH + b)) * DMODEL + co;
    float* out1 = ctx + ((size_t)(row1 * BATCH + b)) * DMODEL + co;
    #pragma unroll
    for (int nf = 0; nf < 2; nf++) {
        int c = nf * 8 + 2 * tg;
        *(float2*)(out0 + c) = make_float2(o[nf][0] * inv0, o[nf][1] * inv0);
        *(float2*)(out1 + c) = make_float2(o[nf][2] * inv1, o[nf][3] * inv1);
    }
}

// ---------------- LayerNorm over D=256, in place ----------------
__global__ void __launch_bounds__(256)
ln_kernel(float* __restrict__ x, const float* __restrict__ w,
          const float* __restrict__ b) {
    __shared__ float red[2][8];
    __shared__ float stats[2];
    int r = blockIdx.x, c = threadIdx.x;
    float v = x[(size_t)r * DMODEL + c];
    float s = v, sq = v * v;
    #pragma unroll
    for (int off = 16; off; off >>= 1) {
        s  += __shfl_xor_sync(0xffffffffu, s,  off);
        sq += __shfl_xor_sync(0xffffffffu, sq, off);
    }
    int warp = c >> 5, lane = c & 31;
    if (lane == 0) { red[0][warp] = s; red[1][warp] = sq; }
    __syncthreads();
    if (c == 0) {
        float ts = 0.f, tq = 0.f;
        #pragma unroll
        for (int i = 0; i < 8; i++) { ts += red[0][i]; tq += red[1][i]; }
        float mean = ts * (1.f / 256.f);
        float var  = tq * (1.f / 256.f) - mean * mean;
        stats[0] = mean;
        stats[1] = rsqrtf(var + 1e-5f);
    }
    __syncthreads();
    x[(size_t)r * DMODEL + c] = (v - stats[0]) * stats[1] * w[c] + b[c];
}

// ---------------- host orchestration ----------------
extern "C" void kernel_launch(void* const* d_in, const int* in_sizes, int n_in,
                              void* d_out, int out_size) {
    const float* src   = (const float*)d_in[0];
    const int*   ei    = (const int*)  d_in[1];
    const float* gcn_w = (const float*)d_in[2];
    const float* gcn_b = (const float*)d_in[3];
    const float* fc_w  = (const float*)d_in[4];
    const float* fc_b  = (const float*)d_in[5];
    const float* wq = (const float*)d_in[6];  const float* bq = (const float*)d_in[7];
    const float* wk = (const float*)d_in[8];  const float* bk = (const float*)d_in[9];
    const float* wv = (const float*)d_in[10]; const float* bv = (const float*)d_in[11];
    const float* wo = (const float*)d_in[12]; const float* bo = (const float*)d_in[13];
    const float* ln1w = (const float*)d_in[14]; const float* ln1b = (const float*)d_in[15];
    const float* fw1  = (const float*)d_in[16]; const float* fb1  = (const float*)d_in[17];
    const float* fw2  = (const float*)d_in[18]; const float* fb2  = (const float*)d_in[19];
    const float* ln2w = (const float*)d_in[20]; const float* ln2b = (const float*)d_in[21];
    const float* dw   = (const float*)d_in[22]; const float* db   = (const float*)d_in[23];
    float* out = (float*)d_out;
    int E = in_sizes[1] / 2;

    float *pA, *psrcp, *ppe, *px, *pqkv, *pctx, *px1, *ph, *px2;
    float *pweffT, *pbeff, *pqkvT, *pbqkv, *pwoT, *pfw1T, *pfw2T, *pdecT;
    cudaGetSymbolAddress((void**)&pA,     g_Ahat);
    cudaGetSymbolAddress((void**)&psrcp,  g_srcp);
    cudaGetSymbolAddress((void**)&ppe,    g_pe);
    cudaGetSymbolAddress((void**)&px,     g_x);
    cudaGetSymbolAddress((void**)&pqkv,   g_qkv);
    cudaGetSymbolAddress((void**)&pctx,   g_ctx);
    cudaGetSymbolAddress((void**)&px1,    g_x1);
    cudaGetSymbolAddress((void**)&ph,     g_h);
    cudaGetSymbolAddress((void**)&px2,    g_x2);
    cudaGetSymbolAddress((void**)&pweffT, g_weffT);
    cudaGetSymbolAddress((void**)&pbeff,  g_beff);
    cudaGetSymbolAddress((void**)&pqkvT,  g_qkvT);
    cudaGetSymbolAddress((void**)&pbqkv,  g_bqkv);
    cudaGetSymbolAddress((void**)&pwoT,   g_woT);
    cudaGetSymbolAddress((void**)&pfw1T,  g_fw1T);
    cudaGetSymbolAddress((void**)&pfw2T,  g_fw2T);
    cudaGetSymbolAddress((void**)&pdecT,  g_decT);

    cudaFuncSetAttribute(mma_gemm_big<0>, cudaFuncAttributeMaxDynamicSharedMemorySize, GEMMB_SMEM);
    cudaFuncSetAttribute(mma_gemm_big<1>, cudaFuncAttributeMaxDynamicSharedMemorySize, GEMMB_SMEM);
    cudaFuncSetAttribute(mma_gemm_big<2>, cudaFuncAttributeMaxDynamicSharedMemorySize, GEMMB_SMEM);
    cudaFuncSetAttribute(mma_gemm_big<3>, cudaFuncAttributeMaxDynamicSharedMemorySize, GEMMB_SMEM);
    cudaFuncSetAttribute(mma_gemm_big<4>, cudaFuncAttributeMaxDynamicSharedMemorySize, GEMMB_SMEM);

    // 0: fused weight prep + src repack + PE table
    prep_kernel<<<(PREP_TOTAL + 255) / 256, 256>>>(
        wq, wk, wv, wo, fw1, fw2, dw, bq, bk, bv, src,
        pqkvT, pwoT, pfw1T, pfw2T, pdecT, pbqkv, psrcp, ppe);
    // 1-2: A_hat, fused GCN+fc weight
    build_ahat_kernel<<<1, 128>>>(ei, E, pA);
    weff_kernel<<<INDIM, 256>>>(pA, gcn_w, gcn_b, fc_w, fc_b, pweffT, pbeff);

    // 3: fc (GCN folded) + bias + PE-table -> x
    mma_gemm_big<1><<<dim3(2, 64), 512, GEMMB_SMEM>>>(psrcp, pweffT, pbeff, ppe,
                                                      px, KPAD_FC, DMODEL, DMODEL);
    // 4: fused QKV
    mma_gemm_big<0><<<dim3(6, 64), 512, GEMMB_SMEM>>>(px, pqkvT, pbqkv, nullptr,
                                                      pqkv, DMODEL, 3 * DMODEL, 3 * DMODEL);
    // 5: tensor-core flash attention
    attn_mma_kernel<<<dim3(BATCH * NHEAD, T_LEN / 64), 128>>>(pqkv, pctx);

    // 6-7: O-proj + residual(x) -> pre-LN1; LN1 in place
    mma_gemm_big<3><<<dim3(2, 64), 512, GEMMB_SMEM>>>(pctx, pwoT, bo, px,
                                                      px1, DMODEL, DMODEL, DMODEL);
    ln_kernel<<<TBROWS, 256>>>(px1, ln1w, ln1b);

    // 8: ffn1 + relu
    mma_gemm_big<2><<<dim3(16, 64), 512, GEMMB_SMEM>>>(px1, pfw1T, fb1, nullptr,
                                                       ph, DMODEL, DFFN, DFFN);
    // 9: ffn2 + residual
    mma_gemm_big<3><<<dim3(2, 64), 512, GEMMB_SMEM>>>(ph, pfw2T, fb2, px1,
                                                      px2, DFFN, DMODEL, DMODEL);
    // 10: LN2 in place
    ln_kernel<<<TBROWS, 256>>>(px2, ln2w, ln2b);

    // 11: decoder (masked N=162)
    mma_gemm_big<4><<<dim3(2, 64), 512, GEMMB_SMEM>>>(px2, pdecT, db, nullptr,
                                                      out, DMODEL, INDIM, INDIM);
}

// round 16
// speedup vs baseline: 1.1108x; 1.1108x over previous
#include <cuda_runtime.h>
#include <math.h>
#include <stdint.h>

// ---------------- problem constants ----------------
#define T_LEN   1024
#define BATCH   8
#define TBROWS  8192          // T*B
#define DMODEL  256
#define NHEAD   16
#define HDIM    16
#define DFFN    2048
#define NNODES  81
#define INDIM   162
#define KPAD_FC 192           // 162 padded to multiple of 32

// ---------------- scratch (static device memory; allocation-free) ----------
__device__ float g_srcp [TBROWS * KPAD_FC];         // padded+rounded src; pad stays 0
__device__ float g_pe   [T_LEN * DMODEL];           // positional encoding table
__device__ float g_x    [TBROWS * DMODEL];          // fc + PE (residual + qkv input)
__device__ float g_qkv  [TBROWS * 3 * DMODEL];      // fused q|k|v, stride 768
__device__ float g_ctx  [TBROWS * DMODEL];          // attention out
__device__ float g_x1   [TBROWS * DMODEL];          // post-LN1 (ffn1 input + ffn2 residual)
__device__ float g_h    [TBROWS * DFFN];            // ffn hidden
__device__ float g_x2   [TBROWS * DMODEL];          // pre-LN2 -> post-LN2 in place

// prepped weights (K-major [N,K], tf32-rounded)
__device__ float g_weffT[DMODEL * KPAD_FC];         // fused GCN+fc weight; k>=162 stays 0
__device__ float g_beff [DMODEL];
__device__ float g_qkvT [3 * DMODEL * DMODEL];      // [768,256]
__device__ float g_bqkv [3 * DMODEL];
__device__ float g_woT  [DMODEL * DMODEL];          // [256,256]
__device__ float g_fw1T [DFFN * DMODEL];            // [2048,256]
__device__ float g_fw2T [DMODEL * DFFN];            // [256,2048]
__device__ float g_decT [256 * DMODEL];             // rows>=162 stay 0

// ---------------- helpers ----------------
__device__ __forceinline__ uint32_t smem_u32(const void* p) {
    return (uint32_t)__cvta_generic_to_shared(p);
}
__device__ __forceinline__ void cp16(uint32_t s, const void* g) {
    asm volatile("cp.async.cg.shared.global [%0], [%1], 16;\n" :: "r"(s), "l"(g));
}
__device__ __forceinline__ void cp_commit() {
    asm volatile("cp.async.commit_group;\n" ::: "memory");
}
template <int N>
__device__ __forceinline__ void cp_wait() {
    asm volatile("cp.async.wait_group %0;\n" :: "n"(N) : "memory");
}
__device__ __forceinline__ uint32_t f2tf32(float f) {
    uint32_t u;
    asm("cvt.rna.tf32.f32 %0, %1;" : "=r"(u) : "f"(f));
    return u;
}
__device__ __forceinline__ float tf32r(float f) { return __uint_as_float(f2tf32(f)); }

__device__ __forceinline__ void ldsm4(uint32_t& r0, uint32_t& r1, uint32_t& r2,
                                      uint32_t& r3, uint32_t addr) {
    asm volatile("ldmatrix.sync.aligned.m8n8.x4.shared.b16 {%0,%1,%2,%3}, [%4];"
                 : "=r"(r0), "=r"(r1), "=r"(r2), "=r"(r3) : "r"(addr));
}

#define MMA_TF32(accv, a0, a1, a2, a3, b0, b1) \
    asm volatile( \
        "mma.sync.aligned.m16n8k8.row.col.f32.tf32.tf32.f32 " \
        "{%0,%1,%2,%3}, {%4,%5,%6,%7}, {%8,%9}, {%0,%1,%2,%3};" \
        : "+f"((accv)[0]), "+f"((accv)[1]), "+f"((accv)[2]), "+f"((accv)[3]) \
        : "r"(a0), "r"(a1), "r"(a2), "r"(a3), "r"(b0), "r"(b1))

// ------- fold GCN into fc (A_hat built per-block in shared memory) ---------
// Each block k (0..161) computes weffT[:,k] and, for k==0, b_eff.
__global__ void weff_kernel(const int* __restrict__ ei, int E,
                            const float* __restrict__ gw,
                            const float* __restrict__ gb,
                            const float* __restrict__ fc_w,
                            const float* __restrict__ fc_b,
                            float* __restrict__ weffT, float* __restrict__ beff) {
    __shared__ float A[NNODES * NNODES];
    __shared__ float dinv[NNODES];
    int k = blockIdx.x;              // 0..161
    int col = threadIdx.x;           // 0..255
    int nt = blockDim.x;

    for (int i = col; i < NNODES * NNODES; i += nt) A[i] = 0.f;
    __syncthreads();
    for (int e = col; e < E; e += nt) {
        int r = ei[e];
        int c = ei[E + e];
        atomicAdd(&A[c * NNODES + r], 1.0f);
    }
    __syncthreads();
    for (int i = col; i < NNODES; i += nt) A[i * NNODES + i] += 1.0f;
    __syncthreads();
    for (int i = col; i < NNODES; i += nt) {
        float s = 0.f;
        for (int j = 0; j < NNODES; j++) s += A[i * NNODES + j];
        dinv[i] = (s > 0.f) ? rsqrtf(s) : 0.f;
    }
    __syncthreads();

    int ck = k / NNODES, jk = k % NNODES;
    float dj = dinv[jk];
    float s0 = 0.f, s1 = 0.f;
    #pragma unroll 3
    for (int i = 0; i < NNODES; i++) {
        float a = dinv[i] * A[i * NNODES + jk] * dj;   // A_hat[i, jk]
        s0 += a * fc_w[i * DMODEL + col];
        s1 += a * fc_w[(NNODES + i) * DMODEL + col];
    }
    float w0 = gw[ck * 2 + 0], w1 = gw[ck * 2 + 1];
    weffT[col * KPAD_FC + k] = tf32r(w0 * s0 + w1 * s1);
    if (k == 0) {
        float bsum = fc_b[col];
        for (int n = 0; n < INDIM; n++)
            bsum += gb[n / NNODES] * fc_w[n * DMODEL + col];
        beff[col] = bsum;
    }
}

// ---------------- fused weight prep + src repack + PE table ----------------
#define R_W    65536                     // 256*256
#define R_FFN  524288                    // 256*2048
#define R_DEC  41472                     // 256*162
#define R_SRC  (TBROWS * KPAD_FC)        // 1572864
#define R_PE   (T_LEN * DMODEL)          // 262144
#define PREP_TOTAL (4*R_W + 2*R_FFN + R_DEC + 768 + R_SRC + R_PE)

__global__ void prep_kernel(const float* __restrict__ wq, const float* __restrict__ wk,
                            const float* __restrict__ wv, const float* __restrict__ wo,
                            const float* __restrict__ fw1, const float* __restrict__ fw2,
                            const float* __restrict__ dw,
                            const float* __restrict__ bq, const float* __restrict__ bk,
                            const float* __restrict__ bv,
                            const float* __restrict__ src,
                            float* __restrict__ qkvT, float* __restrict__ woT,
                            float* __restrict__ fw1T, float* __restrict__ fw2T,
                            float* __restrict__ decT, float* __restrict__ bqkv,
                            float* __restrict__ srcp, float* __restrict__ pe) {
    const float NEG = -0.03597789206f;                     // -ln(10000)/256
    int idx = blockIdx.x * 256 + threadIdx.x;
    if (idx < R_SRC) {                                     // src repack+round
        int tb = idx / KPAD_FC, c = idx - tb * KPAD_FC;
        srcp[idx] = (c < INDIM) ? tf32r(src[tb * INDIM + c]) : 0.f;
        return;
    }
    idx -= R_SRC;
    if (idx < R_PE) {                                      // PE table (exact math)
        int t = idx >> 8, c = idx & 255;
        float dv = expf(NEG * (float)(c & ~1));
        float ang = (float)t * dv;
        pe[idx] = (c & 1) ? cosf(ang) : sinf(ang);
        return;
    }
    idx -= R_PE;
    if (idx < 3 * R_W) {
        int which = idx / R_W, r = idx % R_W;
        int k = r >> 8, n = r & 255;
        const float* w = (which == 0) ? wq : (which == 1) ? wk : wv;
        qkvT[which * R_W + n * 256 + k] = tf32r(w[r]);
        return;
    }
    idx -= 3 * R_W;
    if (idx < R_W) {
        int k = idx >> 8, n = idx & 255;
        woT[n * 256 + k] = tf32r(wo[idx]);
        return;
    }
    idx -= R_W;
    if (idx < R_FFN) {
        int k = idx >> 11, n = idx & 2047;
        fw1T[(size_t)n * 256 + k] = tf32r(fw1[idx]);
        return;
    }
    idx -= R_FFN;
    if (idx < R_FFN) {
        int k = idx >> 8, n = idx & 255;
        fw2T[(size_t)n * 2048 + k] = tf32r(fw2[idx]);
        return;
    }
    idx -= R_FFN;
    if (idx < R_DEC) {
        int k = idx / 162, n = idx % 162;
        decT[n * 256 + k] = tf32r(dw[idx]);
        return;
    }
    idx -= R_DEC;
    if (idx < 768) {
        bqkv[idx] = (idx < 256) ? bq[idx] : (idx < 512) ? bk[idx - 256] : bv[idx - 512];
    }
}

// ------- unified big-tile GEMM: 128x128, 3-stage ring, 256 thr, 2 blk/SM ---
// (R14-verified configuration.)
// A consumed as raw fp32 bits (hardware tf32 truncation).
// EPI: 0 bias, 1 bias+PE-table via res, 2 bias+relu, 3 bias+res,
//      4 bias+masked (n<Nvalid).
#define SROW 36
#define BMB 128
#define BNB 128
#define STAGEB ((BMB + BNB) * SROW)      // 9216 floats
#define GEMMB_SMEM (3 * STAGEB * 4)      // 110592 bytes -> 2 blocks/SM

template <int EPI>
__global__ void __launch_bounds__(256, 2)
mma_gemm_big(const float* __restrict__ A, const float* __restrict__ Bt,
             const float* __restrict__ bias, const float* __restrict__ res,
             float* __restrict__ C, int K, int Cstride, int Nvalid) {
    extern __shared__ float sm[];
    int tid = threadIdx.x;
    int m0 = blockIdx.y * BMB;
    int n0 = blockIdx.x * BNB;
    int warp = tid >> 5, lane = tid & 31;
    int wm = warp & 1, wn = warp >> 1;          // warp = 64 rows x 32 cols
    int g = lane >> 2, tg = lane & 3;

    uint32_t a_off = (uint32_t)((lane & 15) * 144 + (lane >> 4) * 16);
    uint32_t b_off = (uint32_t)((((lane >> 4) << 3) + (lane & 7)) * 144
                                + ((lane >> 3) & 1) * 16);

    const float* A0 = A + (size_t)m0 * K;
    const float* B0 = Bt + (size_t)n0 * K;

    float acc[4][4][4];
    #pragma unroll
    for (int i = 0; i < 4; i++)
        #pragma unroll
        for (int j = 0; j < 4; j++)
            #pragma unroll
            for (int q = 0; q < 4; q++) acc[i][j][q] = 0.f;

    auto load = [&](int c) {
        uint32_t sa = smem_u32(sm) + (uint32_t)((c % 3) * STAGEB * 4);
        uint32_t sb = sa + BMB * SROW * 4;
        const float* Ab = A0 + c * 32;
        const float* Bb = B0 + c * 32;
        #pragma unroll
        for (int i = 0; i < 4; i++) {            // A: 128 rows x 8 slots
            int id = tid + i * 256;
            int r = id >> 3, sl = id & 7;
            cp16(sa + r * 144 + sl * 16, Ab + (size_t)r * K + sl * 4);
        }
        #pragma unroll
        for (int i = 0; i < 4; i++) {            // B: 128 rows x 8 slots
            int id = tid + i * 256;
            int r = id >> 3, sl = id & 7;
            cp16(sb + r * 144 + sl * 16, Bb + (size_t)r * K + sl * 4);
        }
    };

    int NC = K >> 5;
    load(0); cp_commit();
    load(1); cp_commit();

    for (int c = 0; c < NC; c++) {
        cp_wait<1>();                 // group c complete (<=1 newer pending)
        __syncthreads();              // all warps done with stage (c-1)%3
        if (c + 2 < NC) load(c + 2);  // prefetch into stage (c+2)%3 == (c-1)%3
        cp_commit();
        uint32_t sA = smem_u32(sm) + (uint32_t)((c % 3) * STAGEB * 4);
        uint32_t sB = sA + BMB * SROW * 4;
        #pragma unroll
        for (int ks = 0; ks < 4; ks++) {
            uint32_t k0b = ks * 32;
            uint32_t af[4][4], bf[4][2];
            #pragma unroll
            for (int mf = 0; mf < 4; mf++) {
                uint32_t rm = wm * 64 + mf * 16;
                ldsm4(af[mf][0], af[mf][1], af[mf][2], af[mf][3],
                      sA + rm * 144 + k0b + a_off);
            }
            #pragma unroll
            for (int nfp = 0; nfp < 2; nfp++) {
                uint32_t cn = wn * 32 + nfp * 16;
                ldsm4(bf[2 * nfp][0], bf[2 * nfp][1],
                      bf[2 * nfp + 1][0], bf[2 * nfp + 1][1],
                      sB + cn * 144 + k0b + b_off);
            }
            #pragma unroll
            for (int mf = 0; mf < 4; mf++)
                #pragma unroll
                for (int nf = 0; nf < 4; nf++)
                    MMA_TF32(acc[mf][nf], af[mf][0], af[mf][1], af[mf][2], af[mf][3],
                             bf[nf][0], bf[nf][1]);
        }
    }

    #pragma unroll
    for (int mf = 0; mf < 4; mf++) {
        #pragma unroll
        for (int half = 0; half < 2; half++) {
            int gr = m0 + wm * 64 + mf * 16 + g + half * 8;
            #pragma unroll
            for (int nf = 0; nf < 4; nf++) {
                int cb = n0 + wn * 32 + nf * 8 + 2 * tg;
                if (EPI == 4) {
                    float v0 = acc[mf][nf][half * 2 + 0];
                    float v1 = acc[mf][nf][half * 2 + 1];
                    if (cb < Nvalid)
                        C[(size_t)gr * Cstride + cb]     = v0 + bias[cb];
                    if (cb + 1 < Nvalid)
                        C[(size_t)gr * Cstride + cb + 1] = v1 + bias[cb + 1];
                } else {
                    float v0 = acc[mf][nf][half * 2 + 0] + bias[cb];
                    float v1 = acc[mf][nf][half * 2 + 1] + bias[cb + 1];
                    if (EPI == 3) {
                        v0 += res[(size_t)gr * Cstride + cb];
                        v1 += res[(size_t)gr * Cstride + cb + 1];
                    }
                    if (EPI == 2) { v0 = fmaxf(v0, 0.f); v1 = fmaxf(v1, 0.f); }
                    if (EPI == 1) {
                        int t = gr >> 3;
                        float2 p = *(const float2*)&res[(size_t)t * DMODEL + cb];
                        v0 += p.x;
                        v1 += p.y;
                    }
                    *(float2*)&C[(size_t)gr * Cstride + cb] = make_float2(v0, v1);
                }
            }
        }
    }
}

// ---------------- tensor-core causal flash attention ----------------
#define QKV_STRIDE (3 * DMODEL)
#define QK_ST 20
#define PS_ST 68

__global__ void __launch_bounds__(128)
attn_mma_kernel(const float* __restrict__ qkv, float* __restrict__ ctx) {
    __shared__ float Qs[64 * QK_ST];
    __shared__ float Ks[64 * QK_ST];
    __shared__ float Vt[16 * PS_ST];
    __shared__ float Ps[64 * PS_ST];
    int bh = blockIdx.x;
    int b = bh >> 4, h = bh & 15;
    int qt = blockIdx.y;
    int tid = threadIdx.x;
    int w = tid >> 5, lane = tid & 31;
    int g = lane >> 2, tg = lane & 3;
    int co = h * HDIM;

    for (int idx = tid; idx < 256; idx += 128) {
        int r = idx >> 2, qd = idx & 3;
        int t = qt * 64 + r;
        float4 q = *((const float4*)(qkv + ((size_t)(t * BATCH + b)) * QKV_STRIDE + co) + qd);
        *(float4*)&Qs[r * QK_ST + qd * 4] = q;
    }
    __syncthreads();

    uint32_t qa[2][4];
    {
        int r = w * 16 + g;
        #pragma unroll
        for (int ks = 0; ks < 2; ks++) {
            qa[ks][0] = __float_as_uint(Qs[r       * QK_ST + ks * 8 + tg]);
            qa[ks][1] = __float_as_uint(Qs[(r + 8) * QK_ST + ks * 8 + tg]);
            qa[ks][2] = __float_as_uint(Qs[r       * QK_ST + ks * 8 + tg + 4]);
            qa[ks][3] = __float_as_uint(Qs[(r + 8) * QK_ST + ks * 8 + tg + 4]);
        }
    }

    float m0 = -1e30f, m1 = -1e30f, l0 = 0.f, l1 = 0.f;
    float o[2][4] = {};
    int row0 = qt * 64 + w * 16 + g;
    int row1 = row0 + 8;

    for (int kt = 0; kt <= qt; kt++) {
        for (int idx = tid; idx < 256; idx += 128) {
            int r = idx >> 2, qd = idx & 3;
            int t = kt * 64 + r;
            const float* base = qkv + ((size_t)(t * BATCH + b)) * QKV_STRIDE + co;
            float4 kq = *((const float4*)(base + DMODEL) + qd);
            float4 vq = *((const float4*)(base + 2 * DMODEL) + qd);
            *(float4*)&Ks[r * QK_ST + qd * 4] = kq;
            Vt[(qd * 4 + 0) * PS_ST + r] = vq.x;
            Vt[(qd * 4 + 1) * PS_ST + r] = vq.y;
            Vt[(qd * 4 + 2) * PS_ST + r] = vq.z;
            Vt[(qd * 4 + 3) * PS_ST + r] = vq.w;
        }
        __syncthreads();

        float s[8][4] = {};
        #pragma unroll
        for (int ks = 0; ks < 2; ks++) {
            #pragma unroll
            for (int nf = 0; nf < 8; nf++) {
                uint32_t b0 = __float_as_uint(Ks[(nf * 8 + g) * QK_ST + ks * 8 + tg]);
                uint32_t b1 = __float_as_uint(Ks[(nf * 8 + g) * QK_ST + ks * 8 + tg + 4]);
                MMA_TF32(s[nf], qa[ks][0], qa[ks][1], qa[ks][2], qa[ks][3], b0, b1);
            }
        }

        if (kt == qt) {
            #pragma unroll
            for (int nf = 0; nf < 8; nf++) {
                int c = kt * 64 + nf * 8 + 2 * tg;
                s[nf][0] = (c     <= row0) ? s[nf][0] * 0.25f : -1e30f;
                s[nf][1] = (c + 1 <= row0) ? s[nf][1] * 0.25f : -1e30f;
                s[nf][2] = (c     <= row1) ? s[nf][2] * 0.25f : -1e30f;
                s[nf][3] = (c + 1 <= row1) ? s[nf][3] * 0.25f : -1e30f;
            }
        } else {
            #pragma unroll
            for (int nf = 0; nf < 8; nf++) {
                s[nf][0] *= 0.25f; s[nf][1] *= 0.25f;
                s[nf][2] *= 0.25f; s[nf][3] *= 0.25f;
            }
        }

        float mx0 = -1e30f, mx1 = -1e30f;
        #pragma unroll
        for (int nf = 0; nf < 8; nf++) {
            mx0 = fmaxf(mx0, fmaxf(s[nf][0], s[nf][1]));
            mx1 = fmaxf(mx1, fmaxf(s[nf][2], s[nf][3]));
        }
        mx0 = fmaxf(mx0, __shfl_xor_sync(0xffffffffu, mx0, 1));
        mx0 = fmaxf(mx0, __shfl_xor_sync(0xffffffffu, mx0, 2));
        mx1 = fmaxf(mx1, __shfl_xor_sync(0xffffffffu, mx1, 1));
        mx1 = fmaxf(mx1, __shfl_xor_sync(0xffffffffu, mx1, 2));

        float mn0 = fmaxf(m0, mx0), mn1 = fmaxf(m1, mx1);
        float al0 = __expf(m0 - mn0), al1 = __expf(m1 - mn1);
        m0 = mn0; m1 = mn1;

        float sum0 = 0.f, sum1 = 0.f;
        int pr0 = w * 16 + g, pr1 = pr0 + 8;
        #pragma unroll
        for (int nf = 0; nf < 8; nf++) {
            float p0 = __expf(s[nf][0] - mn0);
            float p1 = __expf(s[nf][1] - mn0);
            float p2 = __expf(s[nf][2] - mn1);
            float p3 = __expf(s[nf][3] - mn1);
            sum0 += p0 + p1;
            sum1 += p2 + p3;
            *(float2*)&Ps[pr0 * PS_ST + nf * 8 + 2 * tg] = make_float2(p0, p1);
            *(float2*)&Ps[pr1 * PS_ST + nf * 8 + 2 * tg] = make_float2(p2, p3);
        }
        sum0 += __shfl_xor_sync(0xffffffffu, sum0, 1);
        sum0 += __shfl_xor_sync(0xffffffffu, sum0, 2);
        sum1 += __shfl_xor_sync(0xffffffffu, sum1, 1);
        sum1 += __shfl_xor_sync(0xffffffffu, sum1, 2);
        l0 = l0 * al0 + sum0;
        l1 = l1 * al1 + sum1;

        #pragma unroll
        for (int nf = 0; nf < 2; nf++) {
            o[nf][0] *= al0; o[nf][1] *= al0;
            o[nf][2] *= al1; o[nf][3] *= al1;
        }
        __syncwarp();

        #pragma unroll
        for (int ks = 0; ks < 8; ks++) {
            uint32_t pa0 = __float_as_uint(Ps[pr0 * PS_ST + ks * 8 + tg]);
            uint32_t pa1 = __float_as_uint(Ps[pr1 * PS_ST + ks * 8 + tg]);
            uint32_t pa2 = __float_as_uint(Ps[pr0 * PS_ST + ks * 8 + tg + 4]);
            uint32_t pa3 = __float_as_uint(Ps[pr1 * PS_ST + ks * 8 + tg + 4]);
            #pragma unroll
            for (int nf = 0; nf < 2; nf++) {
                uint32_t b0 = __float_as_uint(Vt[(nf * 8 + g) * PS_ST + ks * 8 + tg]);
                uint32_t b1 = __float_as_uint(Vt[(nf * 8 + g) * PS_ST + ks * 8 + tg + 4]);
                MMA_TF32(o[nf], pa0, pa1, pa2, pa3, b0, b1);
            }
        }
        __syncthreads();
    }

    float inv0 = 1.f / l0, inv1 = 1.f / l1;
    float* out0 = ctx + ((size_t)(row0 * BATCH + b)) * DMODEL + co;
    float* out1 = ctx + ((size_t)(row1 * BATCH + b)) * DMODEL + co;
    #pragma unroll
    for (int nf = 0; nf < 2; nf++) {
        int c = nf * 8 + 2 * tg;
        *(float2*)(out0 + c) = make_float2(o[nf][0] * inv0, o[nf][1] * inv0);
        *(float2*)(out1 + c) = make_float2(o[nf][2] * inv1, o[nf][3] * inv1);
    }
}

// ---------------- LayerNorm over D=256, in place ----------------
__global__ void __launch_bounds__(256)
ln_kernel(float* __restrict__ x, const float* __restrict__ w,
          const float* __restrict__ b) {
    __shared__ float red[2][8];
    __shared__ float stats[2];
    int r = blockIdx.x, c = threadIdx.x;
    float v = x[(size_t)r * DMODEL + c];
    float s = v, sq = v * v;
    #pragma unroll
    for (int off = 16; off; off >>= 1) {
        s  += __shfl_xor_sync(0xffffffffu, s,  off);
        sq += __shfl_xor_sync(0xffffffffu, sq, off);
    }
    int warp = c >> 5, lane = c & 31;
    if (lane == 0) { red[0][warp] = s; red[1][warp] = sq; }
    __syncthreads();
    if (c == 0) {
        float ts = 0.f, tq = 0.f;
        #pragma unroll
        for (int i = 0; i < 8; i++) { ts += red[0][i]; tq += red[1][i]; }
        float mean = ts * (1.f / 256.f);
        float var  = tq * (1.f / 256.f) - mean * mean;
        stats[0] = mean;
        stats[1] = rsqrtf(var + 1e-5f);
    }
    __syncthreads();
    x[(size_t)r * DMODEL + c] = (v - stats[0]) * stats[1] * w[c] + b[c];
}

// ---------------- host orchestration ----------------
extern "C" void kernel_launch(void* const* d_in, const int* in_sizes, int n_in,
                              void* d_out, int out_size) {
    const float* src   = (const float*)d_in[0];
    const int*   ei    = (const int*)  d_in[1];
    const float* gcn_w = (const float*)d_in[2];
    const float* gcn_b = (const float*)d_in[3];
    const float* fc_w  = (const float*)d_in[4];
    const float* fc_b  = (const float*)d_in[5];
    const float* wq = (const float*)d_in[6];  const float* bq = (const float*)d_in[7];
    const float* wk = (const float*)d_in[8];  const float* bk = (const float*)d_in[9];
    const float* wv = (const float*)d_in[10]; const float* bv = (const float*)d_in[11];
    const float* wo = (const float*)d_in[12]; const float* bo = (const float*)d_in[13];
    const float* ln1w = (const float*)d_in[14]; const float* ln1b = (const float*)d_in[15];
    const float* fw1  = (const float*)d_in[16]; const float* fb1  = (const float*)d_in[17];
    const float* fw2  = (const float*)d_in[18]; const float* fb2  = (const float*)d_in[19];
    const float* ln2w = (const float*)d_in[20]; const float* ln2b = (const float*)d_in[21];
    const float* dw   = (const float*)d_in[22]; const float* db   = (const float*)d_in[23];
    float* out = (float*)d_out;
    int E = in_sizes[1] / 2;

    float *psrcp, *ppe, *px, *pqkv, *pctx, *px1, *ph, *px2;
    float *pweffT, *pbeff, *pqkvT, *pbqkv, *pwoT, *pfw1T, *pfw2T, *pdecT;
    cudaGetSymbolAddress((void**)&psrcp,  g_srcp);
    cudaGetSymbolAddress((void**)&ppe,    g_pe);
    cudaGetSymbolAddress((void**)&px,     g_x);
    cudaGetSymbolAddress((void**)&pqkv,   g_qkv);
    cudaGetSymbolAddress((void**)&pctx,   g_ctx);
    cudaGetSymbolAddress((void**)&px1,    g_x1);
    cudaGetSymbolAddress((void**)&ph,     g_h);
    cudaGetSymbolAddress((void**)&px2,    g_x2);
    cudaGetSymbolAddress((void**)&pweffT, g_weffT);
    cudaGetSymbolAddress((void**)&pbeff,  g_beff);
    cudaGetSymbolAddress((void**)&pqkvT,  g_qkvT);
    cudaGetSymbolAddress((void**)&pbqkv,  g_bqkv);
    cudaGetSymbolAddress((void**)&pwoT,   g_woT);
    cudaGetSymbolAddress((void**)&pfw1T,  g_fw1T);
    cudaGetSymbolAddress((void**)&pfw2T,  g_fw2T);
    cudaGetSymbolAddress((void**)&pdecT,  g_decT);

    cudaFuncSetAttribute(mma_gemm_big<0>, cudaFuncAttributeMaxDynamicSharedMemorySize, GEMMB_SMEM);
    cudaFuncSetAttribute(mma_gemm_big<1>, cudaFuncAttributeMaxDynamicSharedMemorySize, GEMMB_SMEM);
    cudaFuncSetAttribute(mma_gemm_big<2>, cudaFuncAttributeMaxDynamicSharedMemorySize, GEMMB_SMEM);
    cudaFuncSetAttribute(mma_gemm_big<3>, cudaFuncAttributeMaxDynamicSharedMemorySize, GEMMB_SMEM);
    cudaFuncSetAttribute(mma_gemm_big<4>, cudaFuncAttributeMaxDynamicSharedMemorySize, GEMMB_SMEM);

    // 0: fused weight prep + src repack + PE table
    prep_kernel<<<(PREP_TOTAL + 255) / 256, 256>>>(
        wq, wk, wv, wo, fw1, fw2, dw, bq, bk, bv, src,
        pqkvT, pwoT, pfw1T, pfw2T, pdecT, pbqkv, psrcp, ppe);
    // 1: fused GCN+fc weight (A_hat built per-block in smem)
    weff_kernel<<<INDIM, 256>>>(ei, E, gcn_w, gcn_b, fc_w, fc_b, pweffT, pbeff);

    // 2: fc (GCN folded) + bias + PE-table -> x
    mma_gemm_big<1><<<dim3(2, 64), 256, GEMMB_SMEM>>>(psrcp, pweffT, pbeff, ppe,
                                                      px, KPAD_FC, DMODEL, DMODEL);
    // 3: fused QKV
    mma_gemm_big<0><<<dim3(6, 64), 256, GEMMB_SMEM>>>(px, pqkvT, pbqkv, nullptr,
                                                      pqkv, DMODEL, 3 * DMODEL, 3 * DMODEL);
    // 4: tensor-core flash attention
    attn_mma_kernel<<<dim3(BATCH * NHEAD, T_LEN / 64), 128>>>(pqkv, pctx);

    // 5-6: O-proj + residual(x) -> pre-LN1; LN1 in place
    mma_gemm_big<3><<<dim3(2, 64), 256, GEMMB_SMEM>>>(pctx, pwoT, bo, px,
                                                      px1, DMODEL, DMODEL, DMODEL);
    ln_kernel<<<TBROWS, 256>>>(px1, ln1w, ln1b);

    // 7: ffn1 + relu
    mma_gemm_big<2><<<dim3(16, 64), 256, GEMMB_SMEM>>>(px1, pfw1T, fb1, nullptr,
                                                       ph, DMODEL, DFFN, DFFN);
    // 8: ffn2 + residual
    mma_gemm_big<3><<<dim3(2, 64), 256, GEMMB_SMEM>>>(ph, pfw2T, fb2, px1,
                                                      px2, DFFN, DMODEL, DMODEL);
    // 9: LN2 in place
    ln_kernel<<<TBROWS, 256>>>(px2, ln2w, ln2b);

    // 10: decoder (masked N=162)
    mma_gemm_big<4><<<dim3(2, 64), 256, GEMMB_SMEM>>>(px2, pdecT, db, nullptr,
                                                      out, DMODEL, INDIM, INDIM);
}